// round 12
// baseline (speedup 1.0000x reference)
#include <cuda_runtime.h>
#include <math.h>

// Problem shape (fixed by the reference): x[N,K], w[M,K], out[N,M]
#define N_ 1024
#define K_ 256
#define M_ 1024

// Scratch (allocs forbidden; __device__ globals are the sanctioned path).
// All writes are idempotent across graph replays (same inputs -> same values).
__device__ float        g_bT[K_][M_];     // bT[k][m] = |w[m][k]| (1 MB, L2-resident)
__device__ unsigned int g_bmax_bits;      // bits of max|w| (nonneg fp32 orders as uint)
__device__ float2       g_cand[N_][K_];   // per-row compacted {a, bits(k)} pairs
__device__ int          g_cnt[N_];        // per-row exact candidate count (>=1)

// ---------------------------------------------------------------------------
// Kernel 1: abs + transpose of w + Bmax (R8-proven config).
// 64x64 tiles: grid = (16, 4) = 64 blocks, 256 threads, MLP=4 per thread.
// ---------------------------------------------------------------------------
__global__ void __launch_bounds__(256)
absT_kernel(const float* __restrict__ w) {
    __shared__ float tile[64][65];        // [k][m], +1 pad

    const int bm   = blockIdx.x * 64;
    const int bk   = blockIdx.y * 64;
    const int tid  = threadIdx.x;
    const int lane = tid & 31;

    const int k4 = tid & 15;
    const int m0 = tid >> 4;
    float lmax = 0.0f;
    #pragma unroll
    for (int i = 0; i < 4; i++) {
        const int m = m0 + i * 16;
        const float4 v = reinterpret_cast<const float4*>(
                             &w[(bm + m) * K_ + bk])[k4];
        const float a0 = fabsf(v.x), a1 = fabsf(v.y),
                    a2 = fabsf(v.z), a3 = fabsf(v.w);
        tile[4 * k4 + 0][m] = a0;
        tile[4 * k4 + 1][m] = a1;
        tile[4 * k4 + 2][m] = a2;
        tile[4 * k4 + 3][m] = a3;
        lmax = fmaxf(lmax, fmaxf(fmaxf(a0, a1), fmaxf(a2, a3)));
    }
    const unsigned int wm = __reduce_max_sync(0xffffffffu, __float_as_uint(lmax));
    if (lane == 0) atomicMax(&g_bmax_bits, wm);
    __syncthreads();

    const int m4 = tid & 15;
    const int k0 = tid >> 4;
    #pragma unroll
    for (int i = 0; i < 4; i++) {
        const int k = k0 + i * 16;
        float4 o;
        o.x = tile[k][4 * m4 + 0];
        o.y = tile[k][4 * m4 + 1];
        o.z = tile[k][4 * m4 + 2];
        o.w = tile[k][4 * m4 + 3];
        reinterpret_cast<float4*>(&g_bT[bk + k][bm])[m4] = o;
    }
}

// ---------------------------------------------------------------------------
// Kernel 2: one warp per row. Exact pruning (keep k iff a+Bmax >= amax;
// fp-monotone => exact, ">=" keeps the argmax so cnt >= 1). Exact count,
// NO padding (R11 proved padding costs real time).
// grid = 256 CTAs x 128 threads.
// ---------------------------------------------------------------------------
__global__ void __launch_bounds__(128)
candidates_kernel(const float* __restrict__ x) {
    const int lane = threadIdx.x & 31;
    const int n    = blockIdx.x * 4 + (threadIdx.x >> 5);

    const float4* xr = reinterpret_cast<const float4*>(x + n * K_);
    const float4 v0 = xr[lane * 2];
    const float4 v1 = xr[lane * 2 + 1];
    float av[8];
    av[0] = fabsf(v0.x); av[1] = fabsf(v0.y);
    av[2] = fabsf(v0.z); av[3] = fabsf(v0.w);
    av[4] = fabsf(v1.x); av[5] = fabsf(v1.y);
    av[6] = fabsf(v1.z); av[7] = fabsf(v1.w);

    float lmax = av[0];
    #pragma unroll
    for (int j = 1; j < 8; j++) lmax = fmaxf(lmax, av[j]);
    const float amax = __uint_as_float(
        __reduce_max_sync(0xffffffffu, __float_as_uint(lmax)));
    const float Bmax = __uint_as_float(g_bmax_bits);  // ordered by kernel boundary

    int base = 0;
    #pragma unroll
    for (int j = 0; j < 8; j++) {
        const bool keep = (av[j] + Bmax >= amax);
        const unsigned int bal = __ballot_sync(0xffffffffu, keep);
        if (keep) {
            const int p = base + __popc(bal & ((1u << lane) - 1u));
            g_cand[n][p] = make_float2(av[j], __int_as_float(lane * 8 + j));
        }
        base += __popc(bal);
    }
    if (lane == 0) g_cnt[n] = base;
}

// ---------------------------------------------------------------------------
// Kernel 3: the sweep. grid = 1024 CTAs x 128 threads; warp = (row n, 256-m
// quarter q). Half the warps of R8 -> half the prologue/meta work chip-wide,
// and TWO independent LDG.128 per candidate (2x MLP per warp). Exact cnt.
// ---------------------------------------------------------------------------
__global__ void __launch_bounds__(128)
sweep_kernel(float* __restrict__ out) {
    const int tid  = threadIdx.x;
    const int lane = tid & 31;
    const int q    = tid >> 5;            // m-quarter: 256 m's
    const int n    = blockIdx.x;          // output row

    const int cnt = g_cnt[n];             // uniform LDG, exact

    // quarter base: q*64 float4s into the row; lane offset + lane+32 offset
    const float4* const bbase =
        reinterpret_cast<const float4*>(g_bT) + q * 64 + lane;
    const float2* const cand = g_cand[n];

    float4 acc0 = make_float4(-INFINITY, -INFINITY, -INFINITY, -INFINITY);
    float4 acc1 = acc0;

    for (int b = 0; b < cnt; b += 32) {
        const int lim = min(32, cnt - b);
        float2 p = make_float2(0.0f, 0.0f);
        if (lane < lim) p = cand[b + lane];            // one LDG.64 per lane
        for (int j = 0; j < lim; j++) {
            const float aj = __shfl_sync(0xffffffffu, p.x, j);
            const int   kj = __float_as_int(__shfl_sync(0xffffffffu, p.y, j));
            const float4* bp = bbase + kj * (M_ / 4);
            const float4 b0 = bp[0];                   // independent pair of
            const float4 b1 = bp[32];                  // coalesced LDG.128s
            acc0.x = fmaxf(acc0.x, aj + b0.x);
            acc0.y = fmaxf(acc0.y, aj + b0.y);
            acc0.z = fmaxf(acc0.z, aj + b0.z);
            acc0.w = fmaxf(acc0.w, aj + b0.w);
            acc1.x = fmaxf(acc1.x, aj + b1.x);
            acc1.y = fmaxf(acc1.y, aj + b1.y);
            acc1.z = fmaxf(acc1.z, aj + b1.z);
            acc1.w = fmaxf(acc1.w, aj + b1.w);
        }
    }

    float4* op = reinterpret_cast<float4*>(out + n * M_) + q * 64 + lane;
    op[0]  = acc0;
    op[32] = acc1;
}

// ---------------------------------------------------------------------------
extern "C" void kernel_launch(void* const* d_in, const int* in_sizes, int n_in,
                              void* d_out, int out_size) {
    const float* x = (const float*)d_in[0];   // [N, K] fp32
    const float* w = (const float*)d_in[1];   // [M, K] fp32
    float* out     = (float*)d_out;           // [N, M] fp32

    (void)in_sizes; (void)n_in; (void)out_size;

    absT_kernel<<<dim3(M_ / 64, K_ / 64), 256>>>(w);
    candidates_kernel<<<N_ / 4, 128>>>(x);
    sweep_kernel<<<N_, 128>>>(out);
}

// round 13
// speedup vs baseline: 1.1866x; 1.1866x over previous
#include <cuda_runtime.h>
#include <math.h>

// Problem shape (fixed by the reference): x[N,K], w[M,K], out[N,M]
#define N_ 1024
#define K_ 256
#define M_ 1024

// Scratch (allocs forbidden; __device__ globals are the sanctioned path).
// All writes are idempotent / monotone across graph replays (same inputs ->
// same values), so replays are deterministic.
__device__ float        g_bT[K_][M_];     // bT[k][m] = |w[m][k]| (1 MB, L2-resident)
__device__ unsigned int g_bmaxk[K_];      // per-column max|w[:,k]| bits
                                          // (nonneg fp32 orders as uint; monotone)
__device__ float2       g_cand[N_][K_];   // per-row compacted {a, bits(k)} pairs
__device__ int          g_cnt[N_];        // per-row exact candidate count (>=1)

// ---------------------------------------------------------------------------
// Kernel 1: abs + transpose of w + per-column maxima bmaxk.
// 64(m) x 32(k) tiles -> grid 128 CTAs (16 m-tiles x 8 k-tiles) x 128 threads,
// 4 independent LDG.128 per thread (best-measured absT config, R11: 4.61us).
// ---------------------------------------------------------------------------
__global__ void __launch_bounds__(128)
absT_kernel(const float* __restrict__ w) {
    __shared__ float        tile[32][65];   // [k][m], +1 pad
    __shared__ unsigned int smaxk[32];      // per-k column max within this tile

    const int bid = blockIdx.x;
    const int tid = threadIdx.x;

    const int bm = (bid & 15) * 64;         // m-tile base
    const int bk = (bid >> 4) * 32;         // k-tile base

    if (tid < 32) smaxk[tid] = 0u;

    // phase 1: 4 independent LDG.128; track per-k-column partial maxima
    const int k4 = tid & 7;                 // float4 index along k (cols 4k4..4k4+3)
    float cmax[4] = {0.0f, 0.0f, 0.0f, 0.0f};
    #pragma unroll
    for (int i = 0; i < 4; i++) {
        const int m = (tid >> 3) + i * 16;  // 0..63
        const float4 v = reinterpret_cast<const float4*>(
                             &w[(bm + m) * K_ + bk])[k4];
        const float a0 = fabsf(v.x), a1 = fabsf(v.y),
                    a2 = fabsf(v.z), a3 = fabsf(v.w);
        tile[4 * k4 + 0][m] = a0;
        tile[4 * k4 + 1][m] = a1;
        tile[4 * k4 + 2][m] = a2;
        tile[4 * k4 + 3][m] = a3;
        cmax[0] = fmaxf(cmax[0], a0);
        cmax[1] = fmaxf(cmax[1], a1);
        cmax[2] = fmaxf(cmax[2], a2);
        cmax[3] = fmaxf(cmax[3], a3);
    }
    __syncthreads();                         // tile + smaxk init visible

    // column maxima: spread shared atomics (64-entry space, 32 live)
    #pragma unroll
    for (int c = 0; c < 4; c++)
        atomicMax(&smaxk[4 * k4 + c], __float_as_uint(cmax[c]));

    // phase 2: 4 coalesced STG.128 of the transposed tile
    #pragma unroll
    for (int i = 0; i < 4; i++) {
        const int k  = (tid >> 4) + i * 8;   // 0..31
        const int m4 = tid & 15;             // float4 index along m
        float4 o;
        o.x = tile[k][4 * m4 + 0];
        o.y = tile[k][4 * m4 + 1];
        o.z = tile[k][4 * m4 + 2];
        o.w = tile[k][4 * m4 + 3];
        reinterpret_cast<float4*>(&g_bT[bk + k][bm])[m4] = o;
    }
    __syncthreads();                         // shared atomics complete

    // publish per-column maxima: 32 spread global atomics per CTA
    if (tid < 32) atomicMax(&g_bmaxk[bk + tid], smaxk[tid]);
}

// ---------------------------------------------------------------------------
// Kernel 2: one warp per row. Exact per-column pruning:
//   keep k iff a[n,k] + bmaxk[k] >= amax_n.
// fp-monotone => exact; ">=" keeps the argmax (bmaxk >= 0) so cnt >= 1.
// Tighter than global Bmax -> ~25% fewer candidates. Exact count, no padding.
// grid = 256 CTAs x 128 threads (warp w of CTA b owns row b*4+w).
// ---------------------------------------------------------------------------
__global__ void __launch_bounds__(128)
candidates_kernel(const float* __restrict__ x) {
    const int lane = threadIdx.x & 31;
    const int n    = blockIdx.x * 4 + (threadIdx.x >> 5);

    const float4* xr = reinterpret_cast<const float4*>(x + n * K_);
    const float4 v0 = xr[lane * 2];
    const float4 v1 = xr[lane * 2 + 1];
    float av[8];
    av[0] = fabsf(v0.x); av[1] = fabsf(v0.y);
    av[2] = fabsf(v0.z); av[3] = fabsf(v0.w);
    av[4] = fabsf(v1.x); av[5] = fabsf(v1.y);
    av[6] = fabsf(v1.z); av[7] = fabsf(v1.w);

    // per-column bounds for this lane's 8 k's (k = lane*8 + j)
    const uint4 b0 = reinterpret_cast<const uint4*>(g_bmaxk + lane * 8)[0];
    const uint4 b1 = reinterpret_cast<const uint4*>(g_bmaxk + lane * 8)[1];
    float bk[8];
    bk[0] = __uint_as_float(b0.x); bk[1] = __uint_as_float(b0.y);
    bk[2] = __uint_as_float(b0.z); bk[3] = __uint_as_float(b0.w);
    bk[4] = __uint_as_float(b1.x); bk[5] = __uint_as_float(b1.y);
    bk[6] = __uint_as_float(b1.z); bk[7] = __uint_as_float(b1.w);

    float lmax = av[0];
    #pragma unroll
    for (int j = 1; j < 8; j++) lmax = fmaxf(lmax, av[j]);
    const float amax = __uint_as_float(
        __reduce_max_sync(0xffffffffu, __float_as_uint(lmax)));

    int base = 0;
    #pragma unroll
    for (int j = 0; j < 8; j++) {
        const bool keep = (av[j] + bk[j] >= amax);
        const unsigned int bal = __ballot_sync(0xffffffffu, keep);
        if (keep) {
            const int p = base + __popc(bal & ((1u << lane) - 1u));
            g_cand[n][p] = make_float2(av[j], __int_as_float(lane * 8 + j));
        }
        base += __popc(bal);
    }
    if (lane == 0) g_cnt[n] = base;
}

// ---------------------------------------------------------------------------
// Kernel 3: the sweep (bit-identical structure to R8's best).
// grid = 2048 CTAs x 128 threads; warp = (row, 128-m slice). Candidate
// LDG.128s are mutually independent -> high MLP, minimal instruction count.
// ---------------------------------------------------------------------------
__global__ void __launch_bounds__(128)
sweep_kernel(float* __restrict__ out) {
    const int tid   = threadIdx.x;
    const int lane  = tid & 31;
    const int wid   = tid >> 5;
    const int n     = blockIdx.x >> 1;
    const int slice = ((blockIdx.x & 1) << 2) | wid;  // 0..7

    const int cnt = g_cnt[n];                          // uniform LDG, exact

    const float4* const bbase =
        reinterpret_cast<const float4*>(g_bT) + slice * 32 + lane;
    const float2* const cand = g_cand[n];
    float4 acc = make_float4(-INFINITY, -INFINITY, -INFINITY, -INFINITY);

    for (int b = 0; b < cnt; b += 32) {
        const int lim = min(32, cnt - b);
        float2 p = make_float2(0.0f, 0.0f);
        if (lane < lim) p = cand[b + lane];            // one LDG.64 per lane
        for (int j = 0; j < lim; j++) {
            const float aj = __shfl_sync(0xffffffffu, p.x, j);
            const int   kj = __float_as_int(__shfl_sync(0xffffffffu, p.y, j));
            const float4 v = bbase[kj * (M_ / 4)];     // coalesced, independent
            acc.x = fmaxf(acc.x, aj + v.x);
            acc.y = fmaxf(acc.y, aj + v.y);
            acc.z = fmaxf(acc.z, aj + v.z);
            acc.w = fmaxf(acc.w, aj + v.w);
        }
    }

    reinterpret_cast<float4*>(out + n * M_)[slice * 32 + lane] = acc;
}

// ---------------------------------------------------------------------------
extern "C" void kernel_launch(void* const* d_in, const int* in_sizes, int n_in,
                              void* d_out, int out_size) {
    const float* x = (const float*)d_in[0];   // [N, K] fp32
    const float* w = (const float*)d_in[1];   // [M, K] fp32
    float* out     = (float*)d_out;           // [N, M] fp32

    (void)in_sizes; (void)n_in; (void)out_size;

    absT_kernel<<<128, 128>>>(w);
    candidates_kernel<<<N_ / 4, 128>>>(x);
    sweep_kernel<<<2 * N_, 128>>>(out);
}